// round 2
// baseline (speedup 1.0000x reference)
#include <cuda_runtime.h>
#include <cuda_bf16.h>
#include <cstdint>

// Problem geometry (fixed by the dataset):
//   x:      [128, 55, 55, 96] float32, NHWC
//   kernel: [96, 25, 25]      float32 (depthwise mask, mostly zeros)
//   out = depthwise_xcorr_SAME(x, kernel) + x
#define N_CH   96
#define RF     25
#define HALF   12
#define HH     55
#define WW     55
#define MAX_TAPS 625   // fully general: a channel may have all taps nonzero

// Compacted sparse taps, built on-device from the actual kernel input each call.
__device__ int    g_cnt[N_CH];
__device__ short2 g_off[N_CH * MAX_TAPS];  // (dy-12, dx-12)
__device__ float  g_wgt[N_CH * MAX_TAPS];

// One block per channel; 640 threads cover the 625 taps.
// Deterministic index-ordered compaction via warp ballots + block prefix.
__global__ void compact_taps_kernel(const float* __restrict__ kern) {
    const int c = blockIdx.x;
    const int t = threadIdx.x;            // 0..639
    __shared__ int s_warp_cnt[20];
    __shared__ int s_warp_base[20];

    float w = 0.0f;
    bool nz = false;
    if (t < RF * RF) {
        w = kern[c * (RF * RF) + t];
        nz = (w != 0.0f);
    }
    const unsigned mask = __ballot_sync(0xFFFFFFFFu, nz);
    const int lane = t & 31;
    const int wid  = t >> 5;
    if (lane == 0) s_warp_cnt[wid] = __popc(mask);
    __syncthreads();
    if (t == 0) {
        int s = 0;
        #pragma unroll
        for (int i = 0; i < 20; i++) { s_warp_base[i] = s; s += s_warp_cnt[i]; }
        g_cnt[c] = s;
    }
    __syncthreads();
    if (nz) {
        const int pos = s_warp_base[wid] + __popc(mask & ((1u << lane) - 1u));
        const int dy = t / RF;
        const int dx = t % RF;
        g_off[c * MAX_TAPS + pos] = make_short2((short)(dy - HALF), (short)(dx - HALF));
        g_wgt[c * MAX_TAPS + pos] = w;
    }
}

// One thread per float4 of the NHWC tensor (96 % 4 == 0).
// out = x (vectorized copy) + sparse lateral contribution for channels with taps.
__global__ void contour_kernel(const float* __restrict__ x,
                               float* __restrict__ out,
                               int total4) {
    const int idx = blockIdx.x * blockDim.x + threadIdx.x;
    if (idx >= total4) return;

    // Decode [n][h][w][c4] with c fastest; 24 float4 groups per pixel.
    int c4   = idx % (N_CH / 4);
    int rest = idx / (N_CH / 4);
    const int w = rest % WW;
    rest /= WW;
    const int h = rest % HH;
    const int n = rest / HH;

    const float4 v = reinterpret_cast<const float4*>(x)[idx];
    float acc0 = v.x, acc1 = v.y, acc2 = v.z, acc3 = v.w;

    const int base_c = c4 * 4;
    const float* __restrict__ xplane = x + (size_t)n * (HH * WW * N_CH);

    #pragma unroll
    for (int k = 0; k < 4; k++) {
        const int c = base_c + k;
        const int cnt = __ldg(&g_cnt[c]);
        float a = 0.0f;
        for (int t = 0; t < cnt; t++) {
            const short2 o = g_off[c * MAX_TAPS + t];
            const int yy = h + (int)o.x;
            const int xx = w + (int)o.y;
            if ((unsigned)yy < (unsigned)HH && (unsigned)xx < (unsigned)WW) {
                a += g_wgt[c * MAX_TAPS + t] *
                     __ldg(&xplane[(yy * WW + xx) * N_CH + c]);
            }
        }
        if (k == 0) acc0 += a;
        else if (k == 1) acc1 += a;
        else if (k == 2) acc2 += a;
        else acc3 += a;
    }

    reinterpret_cast<float4*>(out)[idx] = make_float4(acc0, acc1, acc2, acc3);
}

extern "C" void kernel_launch(void* const* d_in, const int* in_sizes, int n_in,
                              void* d_out, int out_size) {
    const float* x    = (const float*)d_in[0];
    const float* kern = (const float*)d_in[1];
    float* out        = (float*)d_out;

    // Pass 1: build the sparse tap lists from the actual kernel input.
    compact_taps_kernel<<<N_CH, 640>>>(kern);

    // Pass 2: fused copy + sparse depthwise conv.
    const int total4 = out_size / 4;
    const int threads = 256;
    const int blocks = (total4 + threads - 1) / threads;
    contour_kernel<<<blocks, threads>>>(x, out, total4);
}

// round 4
// speedup vs baseline: 1.8304x; 1.8304x over previous
#include <cuda_runtime.h>
#include <cuda_bf16.h>
#include <cstdint>

// Geometry (fixed by dataset):
//   x:      [128, 55, 55, 96] float32 NHWC
//   kernel: [96, 25, 25]      float32 (sparse depthwise mask)
//   out = depthwise_xcorr_SAME(x, kernel) + x
#define N_CH   96
#define RF     25
#define HALF   12
#define HH     55
#define WW     55
#define NPIX   (HH * WW)            // 3025
#define NIMG   128
#define IMG_STRIDE (NPIX * N_CH)    // 290400
#define PH     (HH + 2 * HALF)      // 79
#define PW     80                   // 79 padded to 80 for alignment
#define PLANE  (PH * PW * NIMG)     // 808960 floats per channel
#define MAX_TAPS 625

// Compacted taps: delta = (dy*PW + dx)*NIMG (int), weight (bitcast float).
__device__ int  g_cnt[N_CH];
__device__ int2 g_taps[N_CH * MAX_TAPS];

// Transposed padded planes [c][ph][pw][n]. Zero-initialized at module load;
// the padding region is NEVER written, so it stays zero across all replays.
__device__ __align__(16) float g_plane[N_CH * PLANE];

// ---------------------------------------------------------------------------
// 1) Compact nonzero taps per channel (deterministic index order).
// ---------------------------------------------------------------------------
__global__ void compact_taps_kernel(const float* __restrict__ kern) {
    const int c = blockIdx.x;
    const int t = threadIdx.x;            // 0..639
    __shared__ int s_warp_cnt[20];
    __shared__ int s_warp_base[20];

    float w = 0.0f;
    bool nz = false;
    if (t < RF * RF) {
        w = kern[c * (RF * RF) + t];
        nz = (w != 0.0f);
    }
    const unsigned mask = __ballot_sync(0xFFFFFFFFu, nz);
    const int lane = t & 31;
    const int wid  = t >> 5;
    if (lane == 0) s_warp_cnt[wid] = __popc(mask);
    __syncthreads();
    if (t == 0) {
        int s = 0;
        #pragma unroll
        for (int i = 0; i < 20; i++) { s_warp_base[i] = s; s += s_warp_cnt[i]; }
        g_cnt[c] = s;
    }
    __syncthreads();
    if (nz) {
        const int pos = s_warp_base[wid] + __popc(mask & ((1u << lane) - 1u));
        const int dy = t / RF - HALF;
        const int dx = t % RF - HALF;
        g_taps[c * MAX_TAPS + pos] = make_int2((dy * PW + dx) * NIMG,
                                               __float_as_int(w));
    }
}

// ---------------------------------------------------------------------------
// 2) Gather-transpose active channel planes: x[n][p][c] -> plane[c][pad p][n].
//    Writes are coalesced (n innermost). Only active channels do work.
// ---------------------------------------------------------------------------
__global__ void transpose_kernel(const float* __restrict__ x) {
    const int c = blockIdx.y;
    if (g_cnt[c] == 0) return;
    const int j = blockIdx.x * blockDim.x + threadIdx.x;   // pixel*128 + n
    if (j >= NPIX * NIMG) return;
    const int n = j & (NIMG - 1);
    const int p = j >> 7;
    const int h = p / WW;
    const int w = p % WW;
    const float v = __ldg(&x[(size_t)n * IMG_STRIDE + p * N_CH + c]);
    g_plane[c * PLANE + ((h + HALF) * PW + (w + HALF)) * NIMG + n] = v;
}

// ---------------------------------------------------------------------------
// 3) Pure streaming copy out = x (4x float4 per thread, minimal instructions).
// ---------------------------------------------------------------------------
__global__ void copy_kernel(const float4* __restrict__ x,
                            float4* __restrict__ out, int total4) {
    int i = blockIdx.x * (blockDim.x * 4) + threadIdx.x;
    #pragma unroll
    for (int k = 0; k < 4; k++) {
        if (i < total4) out[i] = x[i];
        i += blockDim.x;
    }
}

// ---------------------------------------------------------------------------
// 4) Vectorized sparse depthwise conv over n (8 images per thread),
//    no bounds checks (padded planes), one RED.ADD per output element.
// ---------------------------------------------------------------------------
__global__ void conv_kernel(float* __restrict__ out) {
    const int c = blockIdx.y;
    const int cnt = g_cnt[c];
    if (cnt == 0) return;

    const int tid = threadIdx.x;                 // 128 threads
    const int p = blockIdx.x * 8 + (tid >> 4);   // 8 pixels per block
    if (p >= NPIX) return;
    const int n0 = (tid & 15) * 8;               // 16 chunks x 8 images
    const int h = p / WW;
    const int w = p % WW;

    const float* __restrict__ plane = g_plane + c * PLANE;
    const int base = ((h + HALF) * PW + (w + HALF)) * NIMG + n0;
    const int2* __restrict__ taps = g_taps + c * MAX_TAPS;

    float4 a0 = make_float4(0.f, 0.f, 0.f, 0.f);
    float4 a1 = make_float4(0.f, 0.f, 0.f, 0.f);

    for (int t = 0; t < cnt; t++) {
        const int2 tp = __ldg(&taps[t]);         // uniform -> warp broadcast
        const float wt = __int_as_float(tp.y);
        const float4 v0 = *reinterpret_cast<const float4*>(plane + base + tp.x);
        const float4 v1 = *reinterpret_cast<const float4*>(plane + base + tp.x + 4);
        a0.x += wt * v0.x; a0.y += wt * v0.y; a0.z += wt * v0.z; a0.w += wt * v0.w;
        a1.x += wt * v1.x; a1.y += wt * v1.y; a1.z += wt * v1.z; a1.w += wt * v1.w;
    }

    const int ob = p * N_CH + c;
    float lat[8] = {a0.x, a0.y, a0.z, a0.w, a1.x, a1.y, a1.z, a1.w};
    #pragma unroll
    for (int i = 0; i < 8; i++) {
        atomicAdd(&out[(size_t)(n0 + i) * IMG_STRIDE + ob], lat[i]); // RED.ADD
    }
}

// ---------------------------------------------------------------------------
extern "C" void kernel_launch(void* const* d_in, const int* in_sizes, int n_in,
                              void* d_out, int out_size) {
    const float* x    = (const float*)d_in[0];
    const float* kern = (const float*)d_in[1];
    float* out        = (float*)d_out;

    compact_taps_kernel<<<N_CH, 640>>>(kern);

    {
        dim3 grid((NPIX * NIMG + 255) / 256, N_CH);
        transpose_kernel<<<grid, 256>>>(x);
    }

    const int total4 = out_size / 4;
    {
        const int threads = 256;
        const int blocks = (total4 + threads * 4 - 1) / (threads * 4);
        copy_kernel<<<blocks, threads>>>((const float4*)x, (float4*)out, total4);
    }

    {
        dim3 grid((NPIX + 7) / 8, N_CH);
        conv_kernel<<<grid, 128>>>(out);
    }
}

// round 5
// speedup vs baseline: 1.9569x; 1.0691x over previous
#include <cuda_runtime.h>
#include <cuda_bf16.h>
#include <cstdint>

// Geometry (fixed by dataset):
//   x:      [128, 55, 55, 96] float32 NHWC
//   kernel: [96, 25, 25]      float32 (sparse depthwise mask)
//   out = depthwise_xcorr_SAME(x, kernel) + x
#define N_CH   96
#define RF     25
#define HALF   12
#define HH     55
#define WW     55
#define NPIX   (HH * WW)            // 3025
#define NIMG   128
#define IMG_STRIDE (NPIX * N_CH)    // 290400
#define PH     (HH + 2 * HALF)      // 79
#define PW     80                   // padded to 80
#define PLANE  (PH * PW * NIMG)     // 808960 floats per channel
#define MAX_TAPS 625
#define NG     (N_CH / 4)           // 24 float4 groups per pixel
#define CONV_Y 8                    // blockIdx.y stride over active list

// Device-built sparsity metadata (rebuilt every call, fully data-driven).
__device__ int     g_cnt[N_CH];
__device__ int2    g_taps[N_CH * MAX_TAPS];   // (plane delta, weight bits)
__device__ int     g_active[N_CH];
__device__ int     g_nactive;
__device__ uint8_t g_groupmask[NG];           // bit k: channel 4*g+k active

// Transposed padded planes [c][ph][pw][n]; padding never written => stays 0.
__device__ __align__(16) float g_plane[N_CH * PLANE];
// Lateral result [c][p][n]; only active channels written/read.
__device__ __align__(16) float g_lat[N_CH * NPIX * NIMG];

// ---------------------------------------------------------------------------
// 1) One-block compaction: taps, active list, group bitmask. Deterministic.
// ---------------------------------------------------------------------------
__global__ void compact_kernel(const float* __restrict__ kern) {
    const int c = threadIdx.x;
    if (c < N_CH) {
        int cnt = 0;
        #pragma unroll 5
        for (int t = 0; t < RF * RF; t++) {
            const float w = kern[c * (RF * RF) + t];
            if (w != 0.0f) {
                const int dy = t / RF - HALF;
                const int dx = t % RF - HALF;
                g_taps[c * MAX_TAPS + cnt] =
                    make_int2((dy * PW + dx) * NIMG, __float_as_int(w));
                cnt++;
            }
        }
        g_cnt[c] = cnt;
    }
    __syncthreads();
    if (threadIdx.x == 0) {
        int na = 0;
        for (int cc = 0; cc < N_CH; cc++)
            if (g_cnt[cc] > 0) g_active[na++] = cc;
        g_nactive = na;
        for (int g = 0; g < NG; g++) {
            unsigned m = 0;
            #pragma unroll
            for (int k = 0; k < 4; k++)
                if (g_cnt[4 * g + k] > 0) m |= (1u << k);
            g_groupmask[g] = (uint8_t)m;
        }
    }
}

// ---------------------------------------------------------------------------
// 2) Transpose active planes: x[n][p][c] -> plane[c][pad p][n].
//    One thread per (pixel, n); loops the active list. Writes coalesced.
// ---------------------------------------------------------------------------
__global__ void transpose_kernel(const float* __restrict__ x) {
    const int j = blockIdx.x * blockDim.x + threadIdx.x;
    if (j >= NPIX * NIMG) return;
    const int n = j & (NIMG - 1);
    const int p = j >> 7;
    const int h = p / WW;
    const int w = p % WW;
    const float* __restrict__ xp = x + (size_t)n * IMG_STRIDE + p * N_CH;
    const int pb = ((h + HALF) * PW + (w + HALF)) * NIMG + n;
    const int na = g_nactive;
    for (int i = 0; i < na; i++) {
        const int c = g_active[i];
        g_plane[c * PLANE + pb] = __ldg(xp + c);
    }
}

// ---------------------------------------------------------------------------
// 3) Sparse depthwise conv, vectorized over n (8 images/thread), no bounds
//    checks (padded planes), coalesced plain stores to g_lat. No atomics.
// ---------------------------------------------------------------------------
__global__ void conv_kernel() {
    const int na = g_nactive;
    for (int i = blockIdx.y; i < na; i += CONV_Y) {
        const int c   = g_active[i];
        const int cnt = g_cnt[c];

        const int tid = threadIdx.x;                 // 128 threads
        const int p = blockIdx.x * 8 + (tid >> 4);   // 8 pixels per block
        if (p >= NPIX) continue;
        const int n0 = (tid & 15) * 8;
        const int h = p / WW;
        const int w = p % WW;

        const float* __restrict__ plane = g_plane + c * PLANE;
        const int base = ((h + HALF) * PW + (w + HALF)) * NIMG + n0;
        const int2* __restrict__ taps = g_taps + c * MAX_TAPS;

        float4 a0 = make_float4(0.f, 0.f, 0.f, 0.f);
        float4 a1 = make_float4(0.f, 0.f, 0.f, 0.f);
        for (int t = 0; t < cnt; t++) {
            const int2 tp = __ldg(&taps[t]);
            const float wt = __int_as_float(tp.y);
            const float4 v0 = *reinterpret_cast<const float4*>(plane + base + tp.x);
            const float4 v1 = *reinterpret_cast<const float4*>(plane + base + tp.x + 4);
            a0.x += wt * v0.x; a0.y += wt * v0.y; a0.z += wt * v0.z; a0.w += wt * v0.w;
            a1.x += wt * v1.x; a1.y += wt * v1.y; a1.z += wt * v1.z; a1.w += wt * v1.w;
        }
        float4* __restrict__ lat = reinterpret_cast<float4*>(
            g_lat + (size_t)c * (NPIX * NIMG) + p * NIMG + n0);
        lat[0] = a0;
        lat[1] = a1;
    }
}

// ---------------------------------------------------------------------------
// 4) Fused streaming copy + lateral add: out = x + lateral. Common path is a
//    pure float4 copy + 1 byte mask test; active lane-groups gather from g_lat.
// ---------------------------------------------------------------------------
__global__ void copyadd_kernel(const float4* __restrict__ x,
                               float4* __restrict__ out, int total4) {
    int i = blockIdx.x * (blockDim.x * 4) + threadIdx.x;
    #pragma unroll
    for (int k = 0; k < 4; k++) {
        if (i < total4) {
            float4 v = x[i];
            const int c4 = i % NG;
            const unsigned m = g_groupmask[c4];
            if (m) {
                const int q = i / NG;        // n*NPIX + p
                const int p = q % NPIX;
                const int n = q / NPIX;
                const int cb = c4 * 4;
                const size_t lb = (size_t)p * NIMG + n;
                if (m & 1u) v.x += g_lat[(size_t)(cb + 0) * (NPIX * NIMG) + lb];
                if (m & 2u) v.y += g_lat[(size_t)(cb + 1) * (NPIX * NIMG) + lb];
                if (m & 4u) v.z += g_lat[(size_t)(cb + 2) * (NPIX * NIMG) + lb];
                if (m & 8u) v.w += g_lat[(size_t)(cb + 3) * (NPIX * NIMG) + lb];
            }
            out[i] = v;
        }
        i += blockDim.x;
    }
}

// ---------------------------------------------------------------------------
extern "C" void kernel_launch(void* const* d_in, const int* in_sizes, int n_in,
                              void* d_out, int out_size) {
    const float* x    = (const float*)d_in[0];
    const float* kern = (const float*)d_in[1];
    float* out        = (float*)d_out;

    compact_kernel<<<1, 128>>>(kern);

    transpose_kernel<<<(NPIX * NIMG + 255) / 256, 256>>>(x);

    {
        dim3 grid((NPIX + 7) / 8, CONV_Y);
        conv_kernel<<<grid, 128>>>();
    }

    const int total4 = out_size / 4;
    {
        const int threads = 256;
        const int blocks = (total4 + threads * 4 - 1) / (threads * 4);
        copyadd_kernel<<<blocks, threads>>>((const float4*)x, (float4*)out, total4);
    }
}

// round 6
// speedup vs baseline: 3.3519x; 1.7129x over previous
#include <cuda_runtime.h>
#include <cuda_bf16.h>
#include <cstdint>

// Geometry (fixed by dataset):
//   x:      [128, 55, 55, 96] float32 NHWC
//   kernel: [96, 25, 25]      float32 (sparse depthwise mask)
//   out = depthwise_xcorr_SAME(x, kernel) + x
#define N_CH   96
#define RF     25
#define HALF   12
#define HH     55
#define WW     55
#define NPIX   (HH * WW)            // 3025
#define NIMG   128
#define IMG_STRIDE (NPIX * N_CH)    // 290400
#define PH     (HH + 2 * HALF)      // 79
#define PW     80                   // padded to 80
#define PLANE  (PH * PW * NIMG)     // 808960 floats per channel
#define MAX_TAPS 625
#define NG     (N_CH / 4)           // 24 float4 groups per pixel
#define CONV_Y 8

// Device-built sparsity metadata (rebuilt every call, fully data-driven).
__device__ int     g_cnt[N_CH];
__device__ int2    g_taps[N_CH * MAX_TAPS];   // (plane delta, weight bits)
__device__ int     g_active[N_CH];
__device__ int     g_nactive;
__device__ uint8_t g_groupmask[NG];

// Transposed padded planes [c][ph][pw][n]; padding never written => stays 0.
__device__ __align__(16) float g_plane[N_CH * PLANE];
// Lateral result [c][p][n]; only active channels written/read.
__device__ __align__(16) float g_lat[N_CH * NPIX * NIMG];

// ---------------------------------------------------------------------------
// 1a) Parallel tap compaction: one block per channel, ballot + block prefix.
// ---------------------------------------------------------------------------
__global__ void compact_taps_kernel(const float* __restrict__ kern) {
    const int c = blockIdx.x;
    const int t = threadIdx.x;            // 0..639
    __shared__ int s_warp_cnt[20];
    __shared__ int s_warp_base[20];

    float w = 0.0f;
    bool nz = false;
    if (t < RF * RF) {
        w = kern[c * (RF * RF) + t];
        nz = (w != 0.0f);
    }
    const unsigned mask = __ballot_sync(0xFFFFFFFFu, nz);
    const int lane = t & 31;
    const int wid  = t >> 5;
    if (lane == 0) s_warp_cnt[wid] = __popc(mask);
    __syncthreads();
    if (t == 0) {
        int s = 0;
        #pragma unroll
        for (int i = 0; i < 20; i++) { s_warp_base[i] = s; s += s_warp_cnt[i]; }
        g_cnt[c] = s;
    }
    __syncthreads();
    if (nz) {
        const int pos = s_warp_base[wid] + __popc(mask & ((1u << lane) - 1u));
        const int dy = t / RF - HALF;
        const int dx = t % RF - HALF;
        g_taps[c * MAX_TAPS + pos] =
            make_int2((dy * PW + dx) * NIMG, __float_as_int(w));
    }
}

// ---------------------------------------------------------------------------
// 1b) Tiny finalize: active list + per-group bitmask (1 warp).
// ---------------------------------------------------------------------------
__global__ void finalize_kernel() {
    if (threadIdx.x == 0) {
        int na = 0;
        #pragma unroll 4
        for (int c = 0; c < N_CH; c++)
            if (g_cnt[c] > 0) g_active[na++] = c;
        g_nactive = na;
    }
    if (threadIdx.x < NG) {
        const int g = threadIdx.x;
        unsigned m = 0;
        #pragma unroll
        for (int k = 0; k < 4; k++)
            if (g_cnt[4 * g + k] > 0) m |= (1u << k);
        g_groupmask[g] = (uint8_t)m;
    }
}

// ---------------------------------------------------------------------------
// 2) Transpose active planes: x[n][p][c] -> plane[c][pad p][n].
//    2 pixels per thread; active list staged in smem; loads independent (MLP).
// ---------------------------------------------------------------------------
__global__ void transpose_kernel(const float* __restrict__ x) {
    __shared__ int s_active[N_CH];
    __shared__ int s_na;
    if (threadIdx.x == 0) s_na = g_nactive;
    if ((int)threadIdx.x < N_CH) s_active[threadIdx.x] = g_active[threadIdx.x];
    __syncthreads();
    const int na = s_na;

    int j = blockIdx.x * (blockDim.x * 2) + threadIdx.x;
    #pragma unroll
    for (int r = 0; r < 2; r++) {
        if (j < NPIX * NIMG) {
            const int n = j & (NIMG - 1);
            const int p = j >> 7;
            const int h = p / WW;
            const int w = p % WW;
            const float* __restrict__ xp = x + (size_t)n * IMG_STRIDE + p * N_CH;
            const int pb = ((h + HALF) * PW + (w + HALF)) * NIMG + n;
            for (int i = 0; i < na; i++) {
                const int c = s_active[i];
                g_plane[c * PLANE + pb] = __ldg(xp + c);
            }
        }
        j += blockDim.x;
    }
}

// ---------------------------------------------------------------------------
// 3) Sparse depthwise conv, vectorized over n (8 images/thread), no bounds
//    checks (padded planes), coalesced stores to g_lat. No atomics.
// ---------------------------------------------------------------------------
__global__ void conv_kernel() {
    const int na = g_nactive;
    for (int i = blockIdx.y; i < na; i += CONV_Y) {
        const int c   = g_active[i];
        const int cnt = g_cnt[c];

        const int tid = threadIdx.x;                 // 128 threads
        const int p = blockIdx.x * 8 + (tid >> 4);   // 8 pixels per block
        if (p >= NPIX) continue;
        const int n0 = (tid & 15) * 8;
        const int h = p / WW;
        const int w = p % WW;

        const float* __restrict__ plane = g_plane + c * PLANE;
        const int base = ((h + HALF) * PW + (w + HALF)) * NIMG + n0;
        const int2* __restrict__ taps = g_taps + c * MAX_TAPS;

        float4 a0 = make_float4(0.f, 0.f, 0.f, 0.f);
        float4 a1 = make_float4(0.f, 0.f, 0.f, 0.f);
        for (int t = 0; t < cnt; t++) {
            const int2 tp = __ldg(&taps[t]);
            const float wt = __int_as_float(tp.y);
            const float4 v0 = *reinterpret_cast<const float4*>(plane + base + tp.x);
            const float4 v1 = *reinterpret_cast<const float4*>(plane + base + tp.x + 4);
            a0.x += wt * v0.x; a0.y += wt * v0.y; a0.z += wt * v0.z; a0.w += wt * v0.w;
            a1.x += wt * v1.x; a1.y += wt * v1.y; a1.z += wt * v1.z; a1.w += wt * v1.w;
        }
        float4* __restrict__ lat = reinterpret_cast<float4*>(
            g_lat + (size_t)c * (NPIX * NIMG) + p * NIMG + n0);
        lat[0] = a0;
        lat[1] = a1;
    }
}

// ---------------------------------------------------------------------------
// 4) Fused streaming copy + lateral add with streaming cache hints:
//    x is touch-once (__ldcs), out is write-once (__stcs); lat stays in L2.
// ---------------------------------------------------------------------------
__global__ void copyadd_kernel(const float4* __restrict__ x,
                               float4* __restrict__ out, int total4) {
    int i = blockIdx.x * (blockDim.x * 4) + threadIdx.x;
    #pragma unroll
    for (int k = 0; k < 4; k++) {
        if (i < total4) {
            float4 v = __ldcs(&x[i]);
            const int c4 = i % NG;
            const unsigned m = g_groupmask[c4];
            if (m) {
                const int q = i / NG;        // n*NPIX + p
                const int p = q % NPIX;
                const int n = q / NPIX;
                const int cb = c4 * 4;
                const size_t lb = (size_t)p * NIMG + n;
                if (m & 1u) v.x += __ldg(&g_lat[(size_t)(cb + 0) * (NPIX * NIMG) + lb]);
                if (m & 2u) v.y += __ldg(&g_lat[(size_t)(cb + 1) * (NPIX * NIMG) + lb]);
                if (m & 4u) v.z += __ldg(&g_lat[(size_t)(cb + 2) * (NPIX * NIMG) + lb]);
                if (m & 8u) v.w += __ldg(&g_lat[(size_t)(cb + 3) * (NPIX * NIMG) + lb]);
            }
            __stcs(&out[i], v);
        }
        i += blockDim.x;
    }
}

// ---------------------------------------------------------------------------
extern "C" void kernel_launch(void* const* d_in, const int* in_sizes, int n_in,
                              void* d_out, int out_size) {
    const float* x    = (const float*)d_in[0];
    const float* kern = (const float*)d_in[1];
    float* out        = (float*)d_out;

    compact_taps_kernel<<<N_CH, 640>>>(kern);
    finalize_kernel<<<1, 32>>>();

    transpose_kernel<<<(NPIX * NIMG + 511) / 512, 256>>>(x);

    {
        dim3 grid((NPIX + 7) / 8, CONV_Y);
        conv_kernel<<<grid, 128>>>();
    }

    const int total4 = out_size / 4;
    {
        const int threads = 256;
        const int blocks = (total4 + threads * 4 - 1) / (threads * 4);
        copyadd_kernel<<<blocks, threads>>>((const float4*)x, (float4*)out, total4);
    }
}